// round 11
// baseline (speedup 1.0000x reference)
#include <cuda_runtime.h>
#include <cuda_bf16.h>
#include <cstdint>
#include <cstddef>
#include <math.h>

// ---------------------------------------------------------------------------
// Problem constants
// ---------------------------------------------------------------------------
#define T_TOK   41472          // 512*81 tokens = 162*256
#define DIM     512
#define HID     2048
#define K_CAT   1536
#define EPSF    1e-5f

// weight segment element offsets inside g_wq
#define OFF_WIN   0            // W_in   [512 ,1536]
#define OFF_WFC1  786432       // W_fc1  [2048, 512]
#define OFF_WFC2  1835008      // W_fc2  [512 ,2048]
#define OFF_WZ    2883584      // W_z    [512 , 512]
#define OFF_WM    3145728      // W_mask [1   , 512]
#define WQ_TOTAL  3146240

// GEMM tiling: 256(M) x 128(N) x 64(K) per CTA, 256 threads, warp tile 64x64
#define LDS64        72                       // row stride (bf16): 144B, odd chunks -> conflict-free
#define A_TILE_ELEMS (256 * LDS64)
#define B_TILE_ELEMS (128 * LDS64)
#define STAGE_ELEMS  (A_TILE_ELEMS + B_TILE_ELEMS)   // 384*72 = 27648 elems
#define NSTAGE       4
#define DSM_BYTES    (NSTAGE * STAGE_ELEMS * 2)      // 221184 bytes

// ---------------------------------------------------------------------------
// Scratch (device globals; allocation-free)
// ---------------------------------------------------------------------------
__device__ __align__(256) __nv_bfloat16 g_qact[(size_t)T_TOK * 2048]; // quantized acts (bf16-held ints)
__device__ __align__(256) float         g_h  [(size_t)T_TOK * DIM];   // h (residual-updated in place)
__device__ __align__(256) float         g_g  [(size_t)T_TOK * HID];   // gelu output
__device__ __align__(256) __nv_bfloat16 g_wq [WQ_TOTAL];              // ternary weights as bf16
__device__ __align__(256) float         g_ainv[T_TOK];                // per-token absmax/127
__device__ __align__(256) float         g_wmean[5];                   // clip(mean|w|,1e-5)
__device__ __align__(256) double        g_part[5 * 64];               // deterministic partials

// ---------------------------------------------------------------------------
// Small helpers
// ---------------------------------------------------------------------------
__device__ __forceinline__ uint32_t smem_u32(const void* p) {
    uint32_t a;
    asm("{ .reg .u64 t; cvta.to.shared.u64 t, %1; cvt.u32.u64 %0, t; }" : "=r"(a) : "l"(p));
    return a;
}
__device__ __forceinline__ void cp16(uint32_t s, const void* g) {
    asm volatile("cp.async.cg.shared.global [%0], [%1], 16;" :: "r"(s), "l"(g));
}
__device__ __forceinline__ void cp_commit() {
    asm volatile("cp.async.commit_group;" ::: "memory");
}
__device__ __forceinline__ void cp_wait2() {
    asm volatile("cp.async.wait_group 2;" ::: "memory");
}
__device__ __forceinline__ void cp_wait1() {
    asm volatile("cp.async.wait_group 1;" ::: "memory");
}
__device__ __forceinline__ void cp_wait0() {
    asm volatile("cp.async.wait_group 0;" ::: "memory");
}
__device__ __forceinline__ void ldsm4(uint32_t* r, uint32_t a) {
    asm volatile("ldmatrix.sync.aligned.m8n8.x4.shared.b16 {%0,%1,%2,%3}, [%4];"
                 : "=r"(r[0]), "=r"(r[1]), "=r"(r[2]), "=r"(r[3]) : "r"(a));
}
__device__ __forceinline__ void mma16816(float* c, const uint32_t* a, uint32_t b0, uint32_t b1) {
    asm volatile("mma.sync.aligned.m16n8k16.row.col.f32.bf16.bf16.f32 "
                 "{%0,%1,%2,%3}, {%4,%5,%6,%7}, {%8,%9}, {%0,%1,%2,%3};"
                 : "+f"(c[0]), "+f"(c[1]), "+f"(c[2]), "+f"(c[3])
                 : "r"(a[0]), "r"(a[1]), "r"(a[2]), "r"(a[3]), "r"(b0), "r"(b1));
}
__device__ __forceinline__ float gelu_exact(float v) {
    return 0.5f * v * (1.0f + erff(v * 0.7071067811865476f));
}
__device__ __forceinline__ uint32_t bpack2(float a, float b) {
    __nv_bfloat162 h;
    h.x = __float2bfloat16(a);
    h.y = __float2bfloat16(b);
    return *(uint32_t*)&h;
}
__device__ __forceinline__ float qv(float v, float sc) {
    return fminf(fmaxf(rintf(v * sc), -128.0f), 127.0f);
}

// ---------------------------------------------------------------------------
// Weight stats: deterministic |w| mean per segment (double accumulation)
// ---------------------------------------------------------------------------
__constant__ int c_seglen[5] = {786432, 1048576, 1048576, 262144, 512};

__global__ void k_wpart(const float* w0, const float* w1, const float* w2,
                        const float* w3, const float* w4) {
    __shared__ double red[256];
    int seg = blockIdx.x >> 6, chunk = blockIdx.x & 63;
    const float* w = (seg == 0) ? w0 : (seg == 1) ? w1 : (seg == 2) ? w2 : (seg == 3) ? w3 : w4;
    int len = c_seglen[seg];
    int clen = (len + 63) >> 6;
    int beg = chunk * clen;
    int end = min(beg + clen, len);
    double s = 0.0;
    for (int i = beg + threadIdx.x; i < end; i += 256) s += (double)fabsf(w[i]);
    red[threadIdx.x] = s;
    __syncthreads();
    for (int st = 128; st; st >>= 1) {
        if (threadIdx.x < st) red[threadIdx.x] += red[threadIdx.x + st];
        __syncthreads();
    }
    if (threadIdx.x == 0) g_part[blockIdx.x] = red[0];
}

__global__ void k_wfinal() {
    __shared__ double red[64];
    int seg = blockIdx.x;
    red[threadIdx.x] = g_part[seg * 64 + threadIdx.x];
    __syncthreads();
    for (int st = 32; st; st >>= 1) {
        if (threadIdx.x < st) red[threadIdx.x] += red[threadIdx.x + st];
        __syncthreads();
    }
    if (threadIdx.x == 0)
        g_wmean[seg] = fmaxf((float)(red[0] / (double)c_seglen[seg]), EPSF);
}

__global__ void k_wquant(const float* w0, const float* w1, const float* w2,
                         const float* w3, const float* w4) {
    int i = blockIdx.x * 256 + threadIdx.x;
    if (i >= WQ_TOTAL) return;
    int seg, off;
    const float* w;
    if (i < OFF_WFC1)      { seg = 0; off = i;            w = w0; }
    else if (i < OFF_WFC2) { seg = 1; off = i - OFF_WFC1; w = w1; }
    else if (i < OFF_WZ)   { seg = 2; off = i - OFF_WFC2; w = w2; }
    else if (i < OFF_WM)   { seg = 3; off = i - OFF_WZ;   w = w3; }
    else                   { seg = 4; off = i - OFF_WM;   w = w4; }
    float sc = 1.0f / g_wmean[seg];
    float q = fminf(fmaxf(rintf(w[off] * sc), -1.0f), 1.0f);
    g_wq[i] = __float2bfloat16(q);
}

// ---------------------------------------------------------------------------
// Activation quantization: per-token absmax int8 values held in bf16 (exact).
// 128 threads/token, values kept in registers, float4 in / bf16x2-pair out.
// isrc: 0 -> g_h, 1 -> g_g
// ---------------------------------------------------------------------------
template <int K>
__global__ void __launch_bounds__(128) k_aq_v(int isrc) {
    constexpr int V = K / 512;  // float4 per thread
    __shared__ float sm[4];
    const float4* x4 = (const float4*)(((isrc == 0) ? g_h : g_g) + (size_t)blockIdx.x * K);
    float4 v[V];
    float m = 0.0f;
#pragma unroll
    for (int i = 0; i < V; i++) {
        v[i] = x4[threadIdx.x + i * 128];
        m = fmaxf(m, fmaxf(fmaxf(fabsf(v[i].x), fabsf(v[i].y)),
                           fmaxf(fabsf(v[i].z), fabsf(v[i].w))));
    }
#pragma unroll
    for (int st = 16; st; st >>= 1) m = fmaxf(m, __shfl_xor_sync(0xFFFFFFFFu, m, st));
    if ((threadIdx.x & 31) == 0) sm[threadIdx.x >> 5] = m;
    __syncthreads();
    float amax = fmaxf(fmaxf(fmaxf(sm[0], sm[1]), fmaxf(sm[2], sm[3])), EPSF);
    float sc = 127.0f / amax;
    uint2* q2 = (uint2*)(g_qact + (size_t)blockIdx.x * K);
#pragma unroll
    for (int i = 0; i < V; i++) {
        uint2 u;
        u.x = bpack2(qv(v[i].x, sc), qv(v[i].y, sc));
        u.y = bpack2(qv(v[i].z, sc), qv(v[i].w, sc));
        q2[threadIdx.x + i * 128] = u;
    }
    if (threadIdx.x == 0) g_ainv[blockIdx.x] = amax * (1.0f / 127.0f);
}

// cat([x,y,s], -1) variant, K = 1536
__global__ void __launch_bounds__(128) k_aq_cat(const float* __restrict__ x,
                                                const float* __restrict__ y,
                                                const float* __restrict__ s) {
    __shared__ float sm[4];
    size_t row = blockIdx.x;
    float4 vx = ((const float4*)(x + row * DIM))[threadIdx.x];
    float4 vy = ((const float4*)(y + row * DIM))[threadIdx.x];
    float4 vs = ((const float4*)(s + row * DIM))[threadIdx.x];
    float m = fmaxf(fmaxf(fabsf(vx.x), fabsf(vx.y)), fmaxf(fabsf(vx.z), fabsf(vx.w)));
    m = fmaxf(m, fmaxf(fmaxf(fabsf(vy.x), fabsf(vy.y)), fmaxf(fabsf(vy.z), fabsf(vy.w))));
    m = fmaxf(m, fmaxf(fmaxf(fabsf(vs.x), fabsf(vs.y)), fmaxf(fabsf(vs.z), fabsf(vs.w))));
#pragma unroll
    for (int st = 16; st; st >>= 1) m = fmaxf(m, __shfl_xor_sync(0xFFFFFFFFu, m, st));
    if ((threadIdx.x & 31) == 0) sm[threadIdx.x >> 5] = m;
    __syncthreads();
    float amax = fmaxf(fmaxf(fmaxf(sm[0], sm[1]), fmaxf(sm[2], sm[3])), EPSF);
    float sc = 127.0f / amax;
    uint2* q2 = (uint2*)(g_qact + row * K_CAT);
    uint2 u;
    u.x = bpack2(qv(vx.x, sc), qv(vx.y, sc)); u.y = bpack2(qv(vx.z, sc), qv(vx.w, sc));
    q2[threadIdx.x] = u;
    u.x = bpack2(qv(vy.x, sc), qv(vy.y, sc)); u.y = bpack2(qv(vy.z, sc), qv(vy.w, sc));
    q2[threadIdx.x + 128] = u;
    u.x = bpack2(qv(vs.x, sc), qv(vs.y, sc)); u.y = bpack2(qv(vs.z, sc), qv(vs.w, sc));
    q2[threadIdx.x + 256] = u;
    if (threadIdx.x == 0) g_ainv[row] = amax * (1.0f / 127.0f);
}

// ---------------------------------------------------------------------------
// GEMM: C[m,n] = epi( (sum_k Aq[m,k] * Wq[n,k]) * ainv[m] * wmean[widx] )
// Block 256(M) x 128(N), BK=64, 256 threads (8 warps: 4 wm x 2 wn),
// warp tile 64x64, 4-buffer depth-3 cp.async pipeline, mma.sync bf16.
// EPI: 0 = store, 1 = gelu+store, 2 = residual add
// csel: 0 -> g_h, 1 -> g_g, 2 -> Cext (d_out)
// ---------------------------------------------------------------------------
template <int EPI>
__global__ void __launch_bounds__(256, 1) k_gemm(int woff, int widx, int K, int N,
                                                 int csel, float* Cext) {
    extern __shared__ __align__(16) __nv_bfloat16 dsm[];

    const __nv_bfloat16* __restrict__ A = g_qact;
    const __nv_bfloat16* __restrict__ W = g_wq + woff;
    float* __restrict__ C = (csel == 0) ? g_h : (csel == 1) ? g_g : Cext;

    const int tid  = threadIdx.x;
    const int lane = tid & 31;
    const int wrp  = tid >> 5;
    const int wm   = wrp & 3;           // 4 M-groups (64 rows each)
    const int wn   = wrp >> 2;          // 2 N-groups (64 cols each)
    const int m0   = blockIdx.y * 256;
    const int n0   = blockIdx.x * 128;

    float acc[4][8][4];
#pragma unroll
    for (int a = 0; a < 4; a++)
#pragma unroll
        for (int b = 0; b < 8; b++)
#pragma unroll
            for (int c = 0; c < 4; c++) acc[a][b][c] = 0.0f;

    const int nk = K >> 6;   // BK = 64

    auto load_stage = [&](int ks, int buf) {
        const int k0 = ks << 6;
        __nv_bfloat16* sA = dsm + buf * STAGE_ELEMS;
        __nv_bfloat16* sB = sA + A_TILE_ELEMS;
        // A tile: 256 rows x 8 chunks = 2048 chunks, 256 threads -> 8 each
#pragma unroll
        for (int i = 0; i < 8; i++) {
            int c   = tid + i * 256;
            int row = c >> 3;
            int ch  = c & 7;
            cp16(smem_u32(sA + row * LDS64 + ch * 8),
                 A + (size_t)(m0 + row) * K + k0 + ch * 8);
        }
        // B tile: 128 rows x 8 chunks = 1024 chunks -> 4 each
#pragma unroll
        for (int i = 0; i < 4; i++) {
            int c   = tid + i * 256;
            int row = c >> 3;
            int ch  = c & 7;
            cp16(smem_u32(sB + row * LDS64 + ch * 8),
                 W + (size_t)(n0 + row) * K + k0 + ch * 8);
        }
        cp_commit();
    };

    load_stage(0, 0);
    load_stage(1, 1);
    load_stage(2, 2);

    for (int ks = 0; ks < nk; ks++) {
        const int buf = ks & 3;
        const int rem = nk - ks;
        if (rem >= 3)      cp_wait2();
        else if (rem == 2) cp_wait1();
        else               cp_wait0();
        __syncthreads();
        if (ks + 3 < nk) load_stage(ks + 3, (ks + 3) & 3);

        const uint32_t baseA = smem_u32(dsm + buf * STAGE_ELEMS);
        const uint32_t baseB = baseA + A_TILE_ELEMS * 2u;

#pragma unroll
        for (int kst = 0; kst < 4; kst++) {
            const int kb = kst * 16;
            uint32_t a[4][4];
#pragma unroll
            for (int mf = 0; mf < 4; mf++) {
                int r = wm * 64 + mf * 16 + (lane & 15);
                ldsm4(a[mf], baseA + (uint32_t)(r * LDS64 + kb + (lane >> 4) * 8) * 2u);
            }
#pragma unroll
            for (int nf2 = 0; nf2 < 4; nf2++) {
                int nr = wn * 64 + nf2 * 16 + (lane >> 4) * 8 + (lane & 7);
                uint32_t b[4];
                ldsm4(b, baseB + (uint32_t)(nr * LDS64 + kb + ((lane >> 3) & 1) * 8) * 2u);
#pragma unroll
                for (int mf = 0; mf < 4; mf++) {
                    mma16816(acc[mf][nf2 * 2 + 0], a[mf], b[0], b[1]);
                    mma16816(acc[mf][nf2 * 2 + 1], a[mf], b[2], b[3]);
                }
            }
        }
    }

    // ---------------- epilogue ----------------
    const float ws  = g_wmean[widx];
    const int   tm  = lane >> 2;
    const int   tn2 = (lane & 3) * 2;
#pragma unroll
    for (int mf = 0; mf < 4; mf++) {
        const int r0 = m0 + wm * 64 + mf * 16 + tm;
        const int r1 = r0 + 8;
        const float s0 = g_ainv[r0] * ws;
        const float s1 = g_ainv[r1] * ws;
#pragma unroll
        for (int nf = 0; nf < 8; nf++) {
            const int c0 = n0 + wn * 64 + nf * 8 + tn2;
            const size_t i0 = (size_t)r0 * N + c0;
            const size_t i1 = (size_t)r1 * N + c0;
            float v00 = acc[mf][nf][0] * s0, v01 = acc[mf][nf][1] * s0;
            float v10 = acc[mf][nf][2] * s1, v11 = acc[mf][nf][3] * s1;
            if (EPI == 0) {
                C[i0] = v00; C[i0 + 1] = v01; C[i1] = v10; C[i1 + 1] = v11;
            } else if (EPI == 1) {
                C[i0] = gelu_exact(v00); C[i0 + 1] = gelu_exact(v01);
                C[i1] = gelu_exact(v10); C[i1 + 1] = gelu_exact(v11);
            } else {
                C[i0] += v00; C[i0 + 1] += v01; C[i1] += v10; C[i1 + 1] += v11;
            }
        }
    }
}

// ---------------------------------------------------------------------------
// Mask head: focus = sigmoid( (qh . wmask) * ainv[m] * wmean[4] ), warp/token
// ---------------------------------------------------------------------------
__global__ void k_mask(float* __restrict__ out) {
    const int lane = threadIdx.x & 31;
    const int row  = blockIdx.x * 8 + (threadIdx.x >> 5);
    const __nv_bfloat162* q = (const __nv_bfloat162*)(g_qact + (size_t)row * DIM);
    const __nv_bfloat162* w = (const __nv_bfloat162*)(g_wq + OFF_WM);
    float s = 0.0f;
#pragma unroll
    for (int k = lane; k < DIM / 2; k += 32) {
        __nv_bfloat162 a = q[k], b = w[k];
        s += __bfloat162float(a.x) * __bfloat162float(b.x)
           + __bfloat162float(a.y) * __bfloat162float(b.y);
    }
#pragma unroll
    for (int st = 16; st; st >>= 1) s += __shfl_xor_sync(0xFFFFFFFFu, s, st);
    if (lane == 0) {
        float v = s * g_ainv[row] * g_wmean[4];
        out[row] = 1.0f / (1.0f + expf(-v));
    }
}

// ---------------------------------------------------------------------------
// Launch
// ---------------------------------------------------------------------------
extern "C" void kernel_launch(void* const* d_in, const int* in_sizes, int n_in,
                              void* d_out, int out_size) {
    const float* x   = (const float*)d_in[0];
    const float* y   = (const float*)d_in[1];
    const float* sp  = (const float*)d_in[2];
    const float* win = (const float*)d_in[3];
    const float* wf1 = (const float*)d_in[4];
    const float* wf2 = (const float*)d_in[5];
    const float* wz  = (const float*)d_in[6];
    const float* wmk = (const float*)d_in[7];
    float* out = (float*)d_out;

    cudaFuncSetAttribute(k_gemm<0>, cudaFuncAttributeMaxDynamicSharedMemorySize, DSM_BYTES);
    cudaFuncSetAttribute(k_gemm<1>, cudaFuncAttributeMaxDynamicSharedMemorySize, DSM_BYTES);
    cudaFuncSetAttribute(k_gemm<2>, cudaFuncAttributeMaxDynamicSharedMemorySize, DSM_BYTES);

    // weight quantization (deterministic)
    k_wpart<<<5 * 64, 256>>>(win, wf1, wf2, wz, wmk);
    k_wfinal<<<5, 64>>>();
    k_wquant<<<(WQ_TOTAL + 255) / 256, 256>>>(win, wf1, wf2, wz, wmk);

    // h = bitlinear(cat, W_in)
    k_aq_cat<<<T_TOK, 128>>>(x, y, sp);
    k_gemm<0><<<dim3(DIM / 128, T_TOK / 256), 256, DSM_BYTES>>>(OFF_WIN, 0, K_CAT, DIM, 0, out);

    // g = gelu(bitlinear(h, W_fc1))
    k_aq_v<DIM><<<T_TOK, 128>>>(0);
    k_gemm<1><<<dim3(HID / 128, T_TOK / 256), 256, DSM_BYTES>>>(OFF_WFC1, 1, DIM, HID, 1, out);

    // h += bitlinear(g, W_fc2)
    k_aq_v<HID><<<T_TOK, 128>>>(1);
    k_gemm<2><<<dim3(DIM / 128, T_TOK / 256), 256, DSM_BYTES>>>(OFF_WFC2, 2, HID, DIM, 0, out);

    // z = bitlinear(h, W_z) -> d_out[0 : T*512]
    k_aq_v<DIM><<<T_TOK, 128>>>(0);
    k_gemm<0><<<dim3(DIM / 128, T_TOK / 256), 256, DSM_BYTES>>>(OFF_WZ, 3, DIM, DIM, 2, out);

    // focus_mask -> d_out[T*512 : T*512 + T]
    k_mask<<<T_TOK / 8, 256>>>(out + (size_t)T_TOK * DIM);
}

// round 12
// speedup vs baseline: 1.2215x; 1.2215x over previous
#include <cuda_runtime.h>
#include <cuda_bf16.h>
#include <cstdint>
#include <cstddef>
#include <math.h>

// ---------------------------------------------------------------------------
// Problem constants
// ---------------------------------------------------------------------------
#define T_TOK   41472          // 512*81 tokens = 324*128
#define DIM     512
#define HID     2048
#define K_CAT   1536
#define EPSF    1e-5f

// weight segment element offsets inside g_wq
#define OFF_WIN   0            // W_in   [512 ,1536]
#define OFF_WFC1  786432       // W_fc1  [2048, 512]
#define OFF_WFC2  1835008      // W_fc2  [512 ,2048]
#define OFF_WZ    2883584      // W_z    [512 , 512]
#define OFF_WM    3145728      // W_mask [1   , 512]
#define WQ_TOTAL  3146240

// GEMM tiling: 128x128x64, 256 threads, 3 smem buffers, 2 CTAs/SM
#define LDS64       72                     // row stride (bf16): 144B, odd chunks -> conflict-free
#define TILE_ELEMS  (128 * LDS64)          // 9216 bf16 per tile
#define STAGE_ELEMS (2 * TILE_ELEMS)       // A + B
#define DSM_BYTES   (3 * STAGE_ELEMS * 2)  // 110592 bytes

// ---------------------------------------------------------------------------
// Scratch (device globals; allocation-free)
// ---------------------------------------------------------------------------
__device__ __align__(256) __nv_bfloat16 g_qact[(size_t)T_TOK * 2048]; // quantized acts (bf16-held ints)
__device__ __align__(256) float         g_h  [(size_t)T_TOK * DIM];   // h (residual-updated in place)
__device__ __align__(256) float         g_g  [(size_t)T_TOK * HID];   // gelu output
__device__ __align__(256) __nv_bfloat16 g_wq [WQ_TOTAL];              // ternary weights as bf16
__device__ __align__(256) float         g_ainv[T_TOK];                // per-token absmax/127
__device__ __align__(256) float         g_wmean[5];                   // clip(mean|w|,1e-5)
__device__ __align__(256) double        g_part[5 * 64];               // deterministic partials

// ---------------------------------------------------------------------------
// Small helpers
// ---------------------------------------------------------------------------
__device__ __forceinline__ uint32_t smem_u32(const void* p) {
    uint32_t a;
    asm("{ .reg .u64 t; cvta.to.shared.u64 t, %1; cvt.u32.u64 %0, t; }" : "=r"(a) : "l"(p));
    return a;
}
__device__ __forceinline__ void cp16(uint32_t s, const void* g) {
    asm volatile("cp.async.cg.shared.global [%0], [%1], 16;" :: "r"(s), "l"(g));
}
__device__ __forceinline__ void cp_commit() {
    asm volatile("cp.async.commit_group;" ::: "memory");
}
__device__ __forceinline__ void cp_wait1() {
    asm volatile("cp.async.wait_group 1;" ::: "memory");
}
__device__ __forceinline__ void cp_wait0() {
    asm volatile("cp.async.wait_group 0;" ::: "memory");
}
__device__ __forceinline__ void ldsm4(uint32_t* r, uint32_t a) {
    asm volatile("ldmatrix.sync.aligned.m8n8.x4.shared.b16 {%0,%1,%2,%3}, [%4];"
                 : "=r"(r[0]), "=r"(r[1]), "=r"(r[2]), "=r"(r[3]) : "r"(a));
}
__device__ __forceinline__ void mma16816(float* c, const uint32_t* a, uint32_t b0, uint32_t b1) {
    asm volatile("mma.sync.aligned.m16n8k16.row.col.f32.bf16.bf16.f32 "
                 "{%0,%1,%2,%3}, {%4,%5,%6,%7}, {%8,%9}, {%0,%1,%2,%3};"
                 : "+f"(c[0]), "+f"(c[1]), "+f"(c[2]), "+f"(c[3])
                 : "r"(a[0]), "r"(a[1]), "r"(a[2]), "r"(a[3]), "r"(b0), "r"(b1));
}
__device__ __forceinline__ float gelu_exact(float v) {
    return 0.5f * v * (1.0f + erff(v * 0.7071067811865476f));
}
__device__ __forceinline__ uint32_t bpack2(float a, float b) {
    __nv_bfloat162 h;
    h.x = __float2bfloat16(a);
    h.y = __float2bfloat16(b);
    return *(uint32_t*)&h;
}
__device__ __forceinline__ float qv(float v, float sc) {
    return fminf(fmaxf(rintf(v * sc), -128.0f), 127.0f);
}

// ---------------------------------------------------------------------------
// Weight stats: deterministic |w| mean per segment (double accumulation)
// ---------------------------------------------------------------------------
__constant__ int c_seglen[5] = {786432, 1048576, 1048576, 262144, 512};

__global__ void k_wpart(const float* w0, const float* w1, const float* w2,
                        const float* w3, const float* w4) {
    __shared__ double red[256];
    int seg = blockIdx.x >> 6, chunk = blockIdx.x & 63;
    const float* w = (seg == 0) ? w0 : (seg == 1) ? w1 : (seg == 2) ? w2 : (seg == 3) ? w3 : w4;
    int len = c_seglen[seg];
    int clen = (len + 63) >> 6;
    int beg = chunk * clen;
    int end = min(beg + clen, len);
    double s = 0.0;
    for (int i = beg + threadIdx.x; i < end; i += 256) s += (double)fabsf(w[i]);
    red[threadIdx.x] = s;
    __syncthreads();
    for (int st = 128; st; st >>= 1) {
        if (threadIdx.x < st) red[threadIdx.x] += red[threadIdx.x + st];
        __syncthreads();
    }
    if (threadIdx.x == 0) g_part[blockIdx.x] = red[0];
}

__global__ void k_wfinal() {
    __shared__ double red[64];
    int seg = blockIdx.x;
    red[threadIdx.x] = g_part[seg * 64 + threadIdx.x];
    __syncthreads();
    for (int st = 32; st; st >>= 1) {
        if (threadIdx.x < st) red[threadIdx.x] += red[threadIdx.x + st];
        __syncthreads();
    }
    if (threadIdx.x == 0)
        g_wmean[seg] = fmaxf((float)(red[0] / (double)c_seglen[seg]), EPSF);
}

__global__ void k_wquant(const float* w0, const float* w1, const float* w2,
                         const float* w3, const float* w4) {
    int i = blockIdx.x * 256 + threadIdx.x;
    if (i >= WQ_TOTAL) return;
    int seg, off;
    const float* w;
    if (i < OFF_WFC1)      { seg = 0; off = i;            w = w0; }
    else if (i < OFF_WFC2) { seg = 1; off = i - OFF_WFC1; w = w1; }
    else if (i < OFF_WZ)   { seg = 2; off = i - OFF_WFC2; w = w2; }
    else if (i < OFF_WM)   { seg = 3; off = i - OFF_WZ;   w = w3; }
    else                   { seg = 4; off = i - OFF_WM;   w = w4; }
    float sc = 1.0f / g_wmean[seg];
    float q = fminf(fmaxf(rintf(w[off] * sc), -1.0f), 1.0f);
    g_wq[i] = __float2bfloat16(q);
}

// ---------------------------------------------------------------------------
// Activation quantization: per-token absmax int8 values held in bf16 (exact).
// 128 threads/token, values kept in registers, float4 in / bf16x2-pair out.
// isrc: 0 -> g_h, 1 -> g_g
// ---------------------------------------------------------------------------
template <int K>
__global__ void __launch_bounds__(128) k_aq_v(int isrc) {
    constexpr int V = K / 512;  // float4 per thread
    __shared__ float sm[4];
    const float4* x4 = (const float4*)(((isrc == 0) ? g_h : g_g) + (size_t)blockIdx.x * K);
    float4 v[V];
    float m = 0.0f;
#pragma unroll
    for (int i = 0; i < V; i++) {
        v[i] = x4[threadIdx.x + i * 128];
        m = fmaxf(m, fmaxf(fmaxf(fabsf(v[i].x), fabsf(v[i].y)),
                           fmaxf(fabsf(v[i].z), fabsf(v[i].w))));
    }
#pragma unroll
    for (int st = 16; st; st >>= 1) m = fmaxf(m, __shfl_xor_sync(0xFFFFFFFFu, m, st));
    if ((threadIdx.x & 31) == 0) sm[threadIdx.x >> 5] = m;
    __syncthreads();
    float amax = fmaxf(fmaxf(fmaxf(sm[0], sm[1]), fmaxf(sm[2], sm[3])), EPSF);
    float sc = 127.0f / amax;
    uint2* q2 = (uint2*)(g_qact + (size_t)blockIdx.x * K);
#pragma unroll
    for (int i = 0; i < V; i++) {
        uint2 u;
        u.x = bpack2(qv(v[i].x, sc), qv(v[i].y, sc));
        u.y = bpack2(qv(v[i].z, sc), qv(v[i].w, sc));
        q2[threadIdx.x + i * 128] = u;
    }
    if (threadIdx.x == 0) g_ainv[blockIdx.x] = amax * (1.0f / 127.0f);
}

// cat([x,y,s], -1) variant, K = 1536
__global__ void __launch_bounds__(128) k_aq_cat(const float* __restrict__ x,
                                                const float* __restrict__ y,
                                                const float* __restrict__ s) {
    __shared__ float sm[4];
    size_t row = blockIdx.x;
    float4 vx = ((const float4*)(x + row * DIM))[threadIdx.x];
    float4 vy = ((const float4*)(y + row * DIM))[threadIdx.x];
    float4 vs = ((const float4*)(s + row * DIM))[threadIdx.x];
    float m = fmaxf(fmaxf(fabsf(vx.x), fabsf(vx.y)), fmaxf(fabsf(vx.z), fabsf(vx.w)));
    m = fmaxf(m, fmaxf(fmaxf(fabsf(vy.x), fabsf(vy.y)), fmaxf(fabsf(vy.z), fabsf(vy.w))));
    m = fmaxf(m, fmaxf(fmaxf(fabsf(vs.x), fabsf(vs.y)), fmaxf(fabsf(vs.z), fabsf(vs.w))));
#pragma unroll
    for (int st = 16; st; st >>= 1) m = fmaxf(m, __shfl_xor_sync(0xFFFFFFFFu, m, st));
    if ((threadIdx.x & 31) == 0) sm[threadIdx.x >> 5] = m;
    __syncthreads();
    float amax = fmaxf(fmaxf(fmaxf(sm[0], sm[1]), fmaxf(sm[2], sm[3])), EPSF);
    float sc = 127.0f / amax;
    uint2* q2 = (uint2*)(g_qact + row * K_CAT);
    uint2 u;
    u.x = bpack2(qv(vx.x, sc), qv(vx.y, sc)); u.y = bpack2(qv(vx.z, sc), qv(vx.w, sc));
    q2[threadIdx.x] = u;
    u.x = bpack2(qv(vy.x, sc), qv(vy.y, sc)); u.y = bpack2(qv(vy.z, sc), qv(vy.w, sc));
    q2[threadIdx.x + 128] = u;
    u.x = bpack2(qv(vs.x, sc), qv(vs.y, sc)); u.y = bpack2(qv(vs.z, sc), qv(vs.w, sc));
    q2[threadIdx.x + 256] = u;
    if (threadIdx.x == 0) g_ainv[row] = amax * (1.0f / 127.0f);
}

// ---------------------------------------------------------------------------
// GEMM: C[m,n] = epi( (sum_k Aq[m,k] * Wq[n,k]) * ainv[m] * wmean[widx] )
// Block 128x128, BK=64, 256 threads, 3-buffer depth-2 cp.async pipeline with
// the prefetch fill SPREAD across the 4 kst sub-iterations (LSU smoothing).
// EPI: 0 = store, 1 = gelu+store, 2 = residual add
// csel: 0 -> g_h, 1 -> g_g, 2 -> Cext (d_out)
// ---------------------------------------------------------------------------
template <int EPI>
__global__ void __launch_bounds__(256, 2) k_gemm(int woff, int widx, int K, int N,
                                                 int csel, float* Cext) {
    extern __shared__ __align__(16) __nv_bfloat16 dsm[];

    const __nv_bfloat16* __restrict__ A = g_qact;
    const __nv_bfloat16* __restrict__ W = g_wq + woff;
    float* __restrict__ C = (csel == 0) ? g_h : (csel == 1) ? g_g : Cext;

    const int tid  = threadIdx.x;
    const int lane = tid & 31;
    const int wrp  = tid >> 5;
    const int wm   = wrp & 3;           // 4 warp rows  (32 rows each)
    const int wn   = wrp >> 2;          // 2 warp cols  (64 cols each)
    const int m0   = blockIdx.y * 128;
    const int n0   = blockIdx.x * 128;

    float acc[2][8][4];
#pragma unroll
    for (int a = 0; a < 2; a++)
#pragma unroll
        for (int b = 0; b < 8; b++)
#pragma unroll
            for (int c = 0; c < 4; c++) acc[a][b][c] = 0.0f;

    const int nk = K >> 6;   // BK = 64

    // full fill (prologue): 1024 16B-chunks per tile, 4 per thread per tile
    auto load_stage = [&](int ks, int buf) {
        const int k0 = ks << 6;
        __nv_bfloat16* sA = dsm + buf * STAGE_ELEMS;
        __nv_bfloat16* sB = sA + TILE_ELEMS;
#pragma unroll
        for (int i = 0; i < 4; i++) {
            int c   = tid + i * 256;
            int row = c >> 3;
            int ch  = c & 7;
            cp16(smem_u32(sA + row * LDS64 + ch * 8),
                 A + (size_t)(m0 + row) * K + k0 + ch * 8);
        }
#pragma unroll
        for (int i = 0; i < 4; i++) {
            int c   = tid + i * 256;
            int row = c >> 3;
            int ch  = c & 7;
            cp16(smem_u32(sB + row * LDS64 + ch * 8),
                 W + (size_t)(n0 + row) * K + k0 + ch * 8);
        }
        cp_commit();
    };

    // quarter fill: issued once per kst (2 cp16 per thread)
    auto quarter_fill = [&](int ks, int buf, int q) {
        const int k0 = ks << 6;
        __nv_bfloat16* sA = dsm + buf * STAGE_ELEMS;
        __nv_bfloat16* sB = sA + TILE_ELEMS;
        int c   = tid + q * 256;
        int row = c >> 3;
        int ch  = c & 7;
        cp16(smem_u32(sA + row * LDS64 + ch * 8),
             A + (size_t)(m0 + row) * K + k0 + ch * 8);
        cp16(smem_u32(sB + row * LDS64 + ch * 8),
             W + (size_t)(n0 + row) * K + k0 + ch * 8);
    };

    load_stage(0, 0);
    load_stage(1, 1);

    int buf = 0;
    for (int ks = 0; ks < nk; ks++) {
        if (ks + 1 < nk) cp_wait1(); else cp_wait0();
        __syncthreads();
        const bool pf = (ks + 2 < nk);
        int nb = buf + 2; if (nb >= 3) nb -= 3;

        const uint32_t baseA = smem_u32(dsm + buf * STAGE_ELEMS);
        const uint32_t baseB = baseA + TILE_ELEMS * 2u;

#pragma unroll
        for (int kst = 0; kst < 4; kst++) {
            if (pf) quarter_fill(ks + 2, nb, kst);
            const int kb = kst * 16;
            uint32_t a[2][4];
#pragma unroll
            for (int mf = 0; mf < 2; mf++) {
                int r = wm * 32 + mf * 16 + (lane & 15);
                ldsm4(a[mf], baseA + (uint32_t)(r * LDS64 + kb + (lane >> 4) * 8) * 2u);
            }
#pragma unroll
            for (int nf2 = 0; nf2 < 4; nf2++) {
                int nr = wn * 64 + nf2 * 16 + (lane >> 4) * 8 + (lane & 7);
                uint32_t b[4];
                ldsm4(b, baseB + (uint32_t)(nr * LDS64 + kb + ((lane >> 3) & 1) * 8) * 2u);
#pragma unroll
                for (int mf = 0; mf < 2; mf++) {
                    mma16816(acc[mf][nf2 * 2 + 0], a[mf], b[0], b[1]);
                    mma16816(acc[mf][nf2 * 2 + 1], a[mf], b[2], b[3]);
                }
            }
        }
        if (pf) cp_commit();
        if (++buf == 3) buf = 0;
    }

    // ---------------- epilogue ----------------
    const float ws  = g_wmean[widx];
    const int   tm  = lane >> 2;
    const int   tn2 = (lane & 3) * 2;
#pragma unroll
    for (int mf = 0; mf < 2; mf++) {
        const int r0 = m0 + wm * 32 + mf * 16 + tm;
        const int r1 = r0 + 8;
        const float s0 = g_ainv[r0] * ws;
        const float s1 = g_ainv[r1] * ws;
#pragma unroll
        for (int nf = 0; nf < 8; nf++) {
            const int c0 = n0 + wn * 64 + nf * 8 + tn2;
            const size_t i0 = (size_t)r0 * N + c0;
            const size_t i1 = (size_t)r1 * N + c0;
            float v00 = acc[mf][nf][0] * s0, v01 = acc[mf][nf][1] * s0;
            float v10 = acc[mf][nf][2] * s1, v11 = acc[mf][nf][3] * s1;
            if (EPI == 0) {
                C[i0] = v00; C[i0 + 1] = v01; C[i1] = v10; C[i1 + 1] = v11;
            } else if (EPI == 1) {
                C[i0] = gelu_exact(v00); C[i0 + 1] = gelu_exact(v01);
                C[i1] = gelu_exact(v10); C[i1 + 1] = gelu_exact(v11);
            } else {
                C[i0] += v00; C[i0 + 1] += v01; C[i1] += v10; C[i1 + 1] += v11;
            }
        }
    }
}

// ---------------------------------------------------------------------------
// Mask head: focus = sigmoid( (qh . wmask) * ainv[m] * wmean[4] ), warp/token
// ---------------------------------------------------------------------------
__global__ void k_mask(float* __restrict__ out) {
    const int lane = threadIdx.x & 31;
    const int row  = blockIdx.x * 8 + (threadIdx.x >> 5);
    const __nv_bfloat162* q = (const __nv_bfloat162*)(g_qact + (size_t)row * DIM);
    const __nv_bfloat162* w = (const __nv_bfloat162*)(g_wq + OFF_WM);
    float s = 0.0f;
#pragma unroll
    for (int k = lane; k < DIM / 2; k += 32) {
        __nv_bfloat162 a = q[k], b = w[k];
        s += __bfloat162float(a.x) * __bfloat162float(b.x)
           + __bfloat162float(a.y) * __bfloat162float(b.y);
    }
#pragma unroll
    for (int st = 16; st; st >>= 1) s += __shfl_xor_sync(0xFFFFFFFFu, s, st);
    if (lane == 0) {
        float v = s * g_ainv[row] * g_wmean[4];
        out[row] = 1.0f / (1.0f + expf(-v));
    }
}

// ---------------------------------------------------------------------------
// Launch
// ---------------------------------------------------------------------------
extern "C" void kernel_launch(void* const* d_in, const int* in_sizes, int n_in,
                              void* d_out, int out_size) {
    const float* x   = (const float*)d_in[0];
    const float* y   = (const float*)d_in[1];
    const float* sp  = (const float*)d_in[2];
    const float* win = (const float*)d_in[3];
    const float* wf1 = (const float*)d_in[4];
    const float* wf2 = (const float*)d_in[5];
    const float* wz  = (const float*)d_in[6];
    const float* wmk = (const float*)d_in[7];
    float* out = (float*)d_out;

    cudaFuncSetAttribute(k_gemm<0>, cudaFuncAttributeMaxDynamicSharedMemorySize, DSM_BYTES);
    cudaFuncSetAttribute(k_gemm<1>, cudaFuncAttributeMaxDynamicSharedMemorySize, DSM_BYTES);
    cudaFuncSetAttribute(k_gemm<2>, cudaFuncAttributeMaxDynamicSharedMemorySize, DSM_BYTES);

    // weight quantization (deterministic)
    k_wpart<<<5 * 64, 256>>>(win, wf1, wf2, wz, wmk);
    k_wfinal<<<5, 64>>>();
    k_wquant<<<(WQ_TOTAL + 255) / 256, 256>>>(win, wf1, wf2, wz, wmk);

    // h = bitlinear(cat, W_in)
    k_aq_cat<<<T_TOK, 128>>>(x, y, sp);
    k_gemm<0><<<dim3(DIM / 128, T_TOK / 128), 256, DSM_BYTES>>>(OFF_WIN, 0, K_CAT, DIM, 0, out);

    // g = gelu(bitlinear(h, W_fc1))
    k_aq_v<DIM><<<T_TOK, 128>>>(0);
    k_gemm<1><<<dim3(HID / 128, T_TOK / 128), 256, DSM_BYTES>>>(OFF_WFC1, 1, DIM, HID, 1, out);

    // h += bitlinear(g, W_fc2)
    k_aq_v<HID><<<T_TOK, 128>>>(1);
    k_gemm<2><<<dim3(DIM / 128, T_TOK / 128), 256, DSM_BYTES>>>(OFF_WFC2, 2, HID, DIM, 0, out);

    // z = bitlinear(h, W_z) -> d_out[0 : T*512]
    k_aq_v<DIM><<<T_TOK, 128>>>(0);
    k_gemm<0><<<dim3(DIM / 128, T_TOK / 128), 256, DSM_BYTES>>>(OFF_WZ, 3, DIM, DIM, 2, out);

    // focus_mask -> d_out[T*512 : T*512 + T]
    k_mask<<<T_TOK / 8, 256>>>(out + (size_t)T_TOK * DIM);
}

// round 13
// speedup vs baseline: 1.2265x; 1.0041x over previous
#include <cuda_runtime.h>
#include <cuda_bf16.h>
#include <cstdint>
#include <cstddef>
#include <math.h>

// ---------------------------------------------------------------------------
// Problem constants
// ---------------------------------------------------------------------------
#define T_TOK   41472          // 512*81 tokens = 324*128
#define DIM     512
#define HID     2048
#define K_CAT   1536
#define EPSF    1e-5f

// weight segment element offsets inside g_wq
#define OFF_WIN   0            // W_in   [512 ,1536]
#define OFF_WFC1  786432       // W_fc1  [2048, 512]
#define OFF_WFC2  1835008      // W_fc2  [512 ,2048]
#define OFF_WZ    2883584      // W_z    [512 , 512]
#define OFF_WM    3145728      // W_mask [1   , 512]
#define WQ_TOTAL  3146240

// GEMM tiling: 128x128x64, 256 threads, 3 smem buffers, 2 CTAs/SM
#define LDS64       72                     // row stride (bf16): 144B, odd chunks -> conflict-free
#define TILE_ELEMS  (128 * LDS64)          // 9216 bf16 per tile
#define STAGE_ELEMS (2 * TILE_ELEMS)       // A + B
#define DSM_BYTES   (3 * STAGE_ELEMS * 2)  // 110592 bytes

// ---------------------------------------------------------------------------
// Scratch (device globals; allocation-free)
// ---------------------------------------------------------------------------
__device__ __align__(256) __nv_bfloat16 g_qact[(size_t)T_TOK * 2048]; // quantized acts (bf16-held ints)
__device__ __align__(256) float         g_h  [(size_t)T_TOK * DIM];   // h (residual-updated in place)
__device__ __align__(256) float         g_g  [(size_t)T_TOK * HID];   // gelu output
__device__ __align__(256) __nv_bfloat16 g_wq [WQ_TOTAL];              // ternary weights as bf16
__device__ __align__(256) float         g_ainv[T_TOK];                // per-token absmax/127
__device__ __align__(256) float         g_wmean[5];                   // clip(mean|w|,1e-5)
__device__ __align__(256) double        g_part[5 * 64];               // deterministic partials

// ---------------------------------------------------------------------------
// Small helpers
// ---------------------------------------------------------------------------
__device__ __forceinline__ uint32_t smem_u32(const void* p) {
    uint32_t a;
    asm("{ .reg .u64 t; cvta.to.shared.u64 t, %1; cvt.u32.u64 %0, t; }" : "=r"(a) : "l"(p));
    return a;
}
__device__ __forceinline__ void cp16(uint32_t s, const void* g) {
    asm volatile("cp.async.cg.shared.global [%0], [%1], 16;" :: "r"(s), "l"(g));
}
__device__ __forceinline__ void cp_commit() {
    asm volatile("cp.async.commit_group;" ::: "memory");
}
__device__ __forceinline__ void cp_wait1() {
    asm volatile("cp.async.wait_group 1;" ::: "memory");
}
__device__ __forceinline__ void cp_wait0() {
    asm volatile("cp.async.wait_group 0;" ::: "memory");
}
__device__ __forceinline__ void ldsm4(uint32_t* r, uint32_t a) {
    asm volatile("ldmatrix.sync.aligned.m8n8.x4.shared.b16 {%0,%1,%2,%3}, [%4];"
                 : "=r"(r[0]), "=r"(r[1]), "=r"(r[2]), "=r"(r[3]) : "r"(a));
}
__device__ __forceinline__ void mma16816(float* c, const uint32_t* a, uint32_t b0, uint32_t b1) {
    asm volatile("mma.sync.aligned.m16n8k16.row.col.f32.bf16.bf16.f32 "
                 "{%0,%1,%2,%3}, {%4,%5,%6,%7}, {%8,%9}, {%0,%1,%2,%3};"
                 : "+f"(c[0]), "+f"(c[1]), "+f"(c[2]), "+f"(c[3])
                 : "r"(a[0]), "r"(a[1]), "r"(a[2]), "r"(a[3]), "r"(b0), "r"(b1));
}
__device__ __forceinline__ float gelu_exact(float v) {
    return 0.5f * v * (1.0f + erff(v * 0.7071067811865476f));
}
__device__ __forceinline__ uint32_t bpack2(float a, float b) {
    __nv_bfloat162 h;
    h.x = __float2bfloat16(a);
    h.y = __float2bfloat16(b);
    return *(uint32_t*)&h;
}
__device__ __forceinline__ float qv(float v, float sc) {
    return fminf(fmaxf(rintf(v * sc), -128.0f), 127.0f);
}

// ---------------------------------------------------------------------------
// Weight stats: deterministic |w| mean per segment (double accumulation)
// ---------------------------------------------------------------------------
__constant__ int c_seglen[5] = {786432, 1048576, 1048576, 262144, 512};

__global__ void k_wpart(const float* w0, const float* w1, const float* w2,
                        const float* w3, const float* w4) {
    __shared__ double red[256];
    int seg = blockIdx.x >> 6, chunk = blockIdx.x & 63;
    const float* w = (seg == 0) ? w0 : (seg == 1) ? w1 : (seg == 2) ? w2 : (seg == 3) ? w3 : w4;
    int len = c_seglen[seg];
    int clen = (len + 63) >> 6;
    int beg = chunk * clen;
    int end = min(beg + clen, len);
    double s = 0.0;
    for (int i = beg + threadIdx.x; i < end; i += 256) s += (double)fabsf(w[i]);
    red[threadIdx.x] = s;
    __syncthreads();
    for (int st = 128; st; st >>= 1) {
        if (threadIdx.x < st) red[threadIdx.x] += red[threadIdx.x + st];
        __syncthreads();
    }
    if (threadIdx.x == 0) g_part[blockIdx.x] = red[0];
}

__global__ void k_wfinal() {
    __shared__ double red[64];
    int seg = blockIdx.x;
    red[threadIdx.x] = g_part[seg * 64 + threadIdx.x];
    __syncthreads();
    for (int st = 32; st; st >>= 1) {
        if (threadIdx.x < st) red[threadIdx.x] += red[threadIdx.x + st];
        __syncthreads();
    }
    if (threadIdx.x == 0)
        g_wmean[seg] = fmaxf((float)(red[0] / (double)c_seglen[seg]), EPSF);
}

__global__ void k_wquant(const float* w0, const float* w1, const float* w2,
                         const float* w3, const float* w4) {
    int i = blockIdx.x * 256 + threadIdx.x;
    if (i >= WQ_TOTAL) return;
    int seg, off;
    const float* w;
    if (i < OFF_WFC1)      { seg = 0; off = i;            w = w0; }
    else if (i < OFF_WFC2) { seg = 1; off = i - OFF_WFC1; w = w1; }
    else if (i < OFF_WZ)   { seg = 2; off = i - OFF_WFC2; w = w2; }
    else if (i < OFF_WM)   { seg = 3; off = i - OFF_WZ;   w = w3; }
    else                   { seg = 4; off = i - OFF_WM;   w = w4; }
    float sc = 1.0f / g_wmean[seg];
    float q = fminf(fmaxf(rintf(w[off] * sc), -1.0f), 1.0f);
    g_wq[i] = __float2bfloat16(q);
}

// ---------------------------------------------------------------------------
// Activation quantization: per-token absmax int8 values held in bf16 (exact).
// 128 threads/token, values kept in registers, float4 in / bf16x2-pair out.
// isrc: 0 -> g_h, 1 -> g_g
// ---------------------------------------------------------------------------
template <int K>
__global__ void __launch_bounds__(128) k_aq_v(int isrc) {
    constexpr int V = K / 512;  // float4 per thread
    __shared__ float sm[4];
    const float4* x4 = (const float4*)(((isrc == 0) ? g_h : g_g) + (size_t)blockIdx.x * K);
    float4 v[V];
    float m = 0.0f;
#pragma unroll
    for (int i = 0; i < V; i++) {
        v[i] = x4[threadIdx.x + i * 128];
        m = fmaxf(m, fmaxf(fmaxf(fabsf(v[i].x), fabsf(v[i].y)),
                           fmaxf(fabsf(v[i].z), fabsf(v[i].w))));
    }
#pragma unroll
    for (int st = 16; st; st >>= 1) m = fmaxf(m, __shfl_xor_sync(0xFFFFFFFFu, m, st));
    if ((threadIdx.x & 31) == 0) sm[threadIdx.x >> 5] = m;
    __syncthreads();
    float amax = fmaxf(fmaxf(fmaxf(sm[0], sm[1]), fmaxf(sm[2], sm[3])), EPSF);
    float sc = 127.0f / amax;
    uint2* q2 = (uint2*)(g_qact + (size_t)blockIdx.x * K);
#pragma unroll
    for (int i = 0; i < V; i++) {
        uint2 u;
        u.x = bpack2(qv(v[i].x, sc), qv(v[i].y, sc));
        u.y = bpack2(qv(v[i].z, sc), qv(v[i].w, sc));
        q2[threadIdx.x + i * 128] = u;
    }
    if (threadIdx.x == 0) g_ainv[blockIdx.x] = amax * (1.0f / 127.0f);
}

// cat([x,y,s], -1) variant, K = 1536
__global__ void __launch_bounds__(128) k_aq_cat(const float* __restrict__ x,
                                                const float* __restrict__ y,
                                                const float* __restrict__ s) {
    __shared__ float sm[4];
    size_t row = blockIdx.x;
    float4 vx = ((const float4*)(x + row * DIM))[threadIdx.x];
    float4 vy = ((const float4*)(y + row * DIM))[threadIdx.x];
    float4 vs = ((const float4*)(s + row * DIM))[threadIdx.x];
    float m = fmaxf(fmaxf(fabsf(vx.x), fabsf(vx.y)), fmaxf(fabsf(vx.z), fabsf(vx.w)));
    m = fmaxf(m, fmaxf(fmaxf(fabsf(vy.x), fabsf(vy.y)), fmaxf(fabsf(vy.z), fabsf(vy.w))));
    m = fmaxf(m, fmaxf(fmaxf(fabsf(vs.x), fabsf(vs.y)), fmaxf(fabsf(vs.z), fabsf(vs.w))));
#pragma unroll
    for (int st = 16; st; st >>= 1) m = fmaxf(m, __shfl_xor_sync(0xFFFFFFFFu, m, st));
    if ((threadIdx.x & 31) == 0) sm[threadIdx.x >> 5] = m;
    __syncthreads();
    float amax = fmaxf(fmaxf(fmaxf(sm[0], sm[1]), fmaxf(sm[2], sm[3])), EPSF);
    float sc = 127.0f / amax;
    uint2* q2 = (uint2*)(g_qact + row * K_CAT);
    uint2 u;
    u.x = bpack2(qv(vx.x, sc), qv(vx.y, sc)); u.y = bpack2(qv(vx.z, sc), qv(vx.w, sc));
    q2[threadIdx.x] = u;
    u.x = bpack2(qv(vy.x, sc), qv(vy.y, sc)); u.y = bpack2(qv(vy.z, sc), qv(vy.w, sc));
    q2[threadIdx.x + 128] = u;
    u.x = bpack2(qv(vs.x, sc), qv(vs.y, sc)); u.y = bpack2(qv(vs.z, sc), qv(vs.w, sc));
    q2[threadIdx.x + 256] = u;
    if (threadIdx.x == 0) g_ainv[row] = amax * (1.0f / 127.0f);
}

// ---------------------------------------------------------------------------
// GEMM: C[m,n] = epi( (sum_k Aq[m,k] * Wq[n,k]) * ainv[m] * wmean[widx] )
// Block 128x128, BK=64, 256 threads, 3-buffer depth-2 cp.async pipeline with
// interleaved quarter-fills AND register double-buffering of LDSM fragments
// (A ping-pongs across kst, B ping-pongs across nf2 groups).
// EPI: 0 = store, 1 = gelu+store, 2 = residual add
// csel: 0 -> g_h, 1 -> g_g, 2 -> Cext (d_out)
// ---------------------------------------------------------------------------
template <int EPI>
__global__ void __launch_bounds__(256, 2) k_gemm(int woff, int widx, int K, int N,
                                                 int csel, float* Cext) {
    extern __shared__ __align__(16) __nv_bfloat16 dsm[];

    const __nv_bfloat16* __restrict__ A = g_qact;
    const __nv_bfloat16* __restrict__ W = g_wq + woff;
    float* __restrict__ C = (csel == 0) ? g_h : (csel == 1) ? g_g : Cext;

    const int tid  = threadIdx.x;
    const int lane = tid & 31;
    const int wrp  = tid >> 5;
    const int wm   = wrp & 3;           // 4 warp rows  (32 rows each)
    const int wn   = wrp >> 2;          // 2 warp cols  (64 cols each)
    const int m0   = blockIdx.y * 128;
    const int n0   = blockIdx.x * 128;

    float acc[2][8][4];
#pragma unroll
    for (int a = 0; a < 2; a++)
#pragma unroll
        for (int b = 0; b < 8; b++)
#pragma unroll
            for (int c = 0; c < 4; c++) acc[a][b][c] = 0.0f;

    // per-thread invariant smem element offsets (in bf16 elems) at kb = 0
    uint32_t aOff[2], bOff[4];
#pragma unroll
    for (int mf = 0; mf < 2; mf++)
        aOff[mf] = (uint32_t)((wm * 32 + mf * 16 + (lane & 15)) * LDS64 + (lane >> 4) * 8);
#pragma unroll
    for (int nf2 = 0; nf2 < 4; nf2++)
        bOff[nf2] = (uint32_t)((wn * 64 + nf2 * 16 + (lane >> 4) * 8 + (lane & 7)) * LDS64
                               + ((lane >> 3) & 1) * 8);

    const int nk = K >> 6;   // BK = 64

    // full fill (prologue): 1024 16B-chunks per tile, 4 per thread per tile
    auto load_stage = [&](int ks, int buf) {
        const int k0 = ks << 6;
        __nv_bfloat16* sA = dsm + buf * STAGE_ELEMS;
        __nv_bfloat16* sB = sA + TILE_ELEMS;
#pragma unroll
        for (int i = 0; i < 4; i++) {
            int c   = tid + i * 256;
            int row = c >> 3;
            int ch  = c & 7;
            cp16(smem_u32(sA + row * LDS64 + ch * 8),
                 A + (size_t)(m0 + row) * K + k0 + ch * 8);
        }
#pragma unroll
        for (int i = 0; i < 4; i++) {
            int c   = tid + i * 256;
            int row = c >> 3;
            int ch  = c & 7;
            cp16(smem_u32(sB + row * LDS64 + ch * 8),
                 W + (size_t)(n0 + row) * K + k0 + ch * 8);
        }
        cp_commit();
    };

    // quarter fill: issued once per kst (2 cp16 per thread)
    auto quarter_fill = [&](int ks, int buf, int q) {
        const int k0 = ks << 6;
        __nv_bfloat16* sA = dsm + buf * STAGE_ELEMS;
        __nv_bfloat16* sB = sA + TILE_ELEMS;
        int c   = tid + q * 256;
        int row = c >> 3;
        int ch  = c & 7;
        cp16(smem_u32(sA + row * LDS64 + ch * 8),
             A + (size_t)(m0 + row) * K + k0 + ch * 8);
        cp16(smem_u32(sB + row * LDS64 + ch * 8),
             W + (size_t)(n0 + row) * K + k0 + ch * 8);
    };

    load_stage(0, 0);
    load_stage(1, 1);

    int buf = 0;
    for (int ks = 0; ks < nk; ks++) {
        if (ks + 1 < nk) cp_wait1(); else cp_wait0();
        __syncthreads();
        const bool pf = (ks + 2 < nk);
        int nb = buf + 2; if (nb >= 3) nb -= 3;

        const uint32_t baseA = smem_u32(dsm + buf * STAGE_ELEMS);
        const uint32_t baseB = baseA + TILE_ELEMS * 2u;

        // fragment double buffers
        uint32_t afr[2][2][4];   // [kst parity][mf][reg]
        uint32_t bfr[2][4];      // [nf2 parity][reg]

        // preload kst=0 A pair and first B group
        ldsm4(afr[0][0], baseA + (aOff[0] + 0) * 2u);
        ldsm4(afr[0][1], baseA + (aOff[1] + 0) * 2u);
        ldsm4(bfr[0],    baseB + (bOff[0] + 0) * 2u);

#pragma unroll
        for (int kst = 0; kst < 4; kst++) {
            const int cur = kst & 1;
            const uint32_t kb = (uint32_t)(kst * 16);
            if (pf) quarter_fill(ks + 2, nb, kst);
            if (kst < 3) {  // prefetch next kst's A pair under this kst's MMAs
                ldsm4(afr[cur ^ 1][0], baseA + (aOff[0] + kb + 16) * 2u);
                ldsm4(afr[cur ^ 1][1], baseA + (aOff[1] + kb + 16) * 2u);
            }
#pragma unroll
            for (int nf2 = 0; nf2 < 4; nf2++) {
                const int bb = nf2 & 1;
                if (nf2 < 3) {
                    ldsm4(bfr[bb ^ 1], baseB + (bOff[nf2 + 1] + kb) * 2u);
                } else if (kst < 3) {
                    ldsm4(bfr[bb ^ 1], baseB + (bOff[0] + kb + 16) * 2u);
                }
#pragma unroll
                for (int mf = 0; mf < 2; mf++) {
                    mma16816(acc[mf][nf2 * 2 + 0], afr[cur][mf], bfr[bb][0], bfr[bb][1]);
                    mma16816(acc[mf][nf2 * 2 + 1], afr[cur][mf], bfr[bb][2], bfr[bb][3]);
                }
            }
        }
        if (pf) cp_commit();
        if (++buf == 3) buf = 0;
    }

    // ---------------- epilogue ----------------
    const float ws  = g_wmean[widx];
    const int   tm  = lane >> 2;
    const int   tn2 = (lane & 3) * 2;
#pragma unroll
    for (int mf = 0; mf < 2; mf++) {
        const int r0 = m0 + wm * 32 + mf * 16 + tm;
        const int r1 = r0 + 8;
        const float s0 = g_ainv[r0] * ws;
        const float s1 = g_ainv[r1] * ws;
#pragma unroll
        for (int nf = 0; nf < 8; nf++) {
            const int c0 = n0 + wn * 64 + nf * 8 + tn2;
            const size_t i0 = (size_t)r0 * N + c0;
            const size_t i1 = (size_t)r1 * N + c0;
            float v00 = acc[mf][nf][0] * s0, v01 = acc[mf][nf][1] * s0;
            float v10 = acc[mf][nf][2] * s1, v11 = acc[mf][nf][3] * s1;
            if (EPI == 0) {
                C[i0] = v00; C[i0 + 1] = v01; C[i1] = v10; C[i1 + 1] = v11;
            } else if (EPI == 1) {
                C[i0] = gelu_exact(v00); C[i0 + 1] = gelu_exact(v01);
                C[i1] = gelu_exact(v10); C[i1 + 1] = gelu_exact(v11);
            } else {
                C[i0] += v00; C[i0 + 1] += v01; C[i1] += v10; C[i1 + 1] += v11;
            }
        }
    }
}

// ---------------------------------------------------------------------------
// Mask head: focus = sigmoid( (qh . wmask) * ainv[m] * wmean[4] ), warp/token
// ---------------------------------------------------------------------------
__global__ void k_mask(float* __restrict__ out) {
    const int lane = threadIdx.x & 31;
    const int row  = blockIdx.x * 8 + (threadIdx.x >> 5);
    const __nv_bfloat162* q = (const __nv_bfloat162*)(g_qact + (size_t)row * DIM);
    const __nv_bfloat162* w = (const __nv_bfloat162*)(g_wq + OFF_WM);
    float s = 0.0f;
#pragma unroll
    for (int k = lane; k < DIM / 2; k += 32) {
        __nv_bfloat162 a = q[k], b = w[k];
        s += __bfloat162float(a.x) * __bfloat162float(b.x)
           + __bfloat162float(a.y) * __bfloat162float(b.y);
    }
#pragma unroll
    for (int st = 16; st; st >>= 1) s += __shfl_xor_sync(0xFFFFFFFFu, s, st);
    if (lane == 0) {
        float v = s * g_ainv[row] * g_wmean[4];
        out[row] = 1.0f / (1.0f + expf(-v));
    }
}

// ---------------------------------------------------------------------------
// Launch
// ---------------------------------------------------------------------------
extern "C" void kernel_launch(void* const* d_in, const int* in_sizes, int n_in,
                              void* d_out, int out_size) {
    const float* x   = (const float*)d_in[0];
    const float* y   = (const float*)d_in[1];
    const float* sp  = (const float*)d_in[2];
    const float* win = (const float*)d_in[3];
    const float* wf1 = (const float*)d_in[4];
    const float* wf2 = (const float*)d_in[5];
    const float* wz  = (const float*)d_in[6];
    const float* wmk = (const float*)d_in[7];
    float* out = (float*)d_out;

    cudaFuncSetAttribute(k_gemm<0>, cudaFuncAttributeMaxDynamicSharedMemorySize, DSM_BYTES);
    cudaFuncSetAttribute(k_gemm<1>, cudaFuncAttributeMaxDynamicSharedMemorySize, DSM_BYTES);
    cudaFuncSetAttribute(k_gemm<2>, cudaFuncAttributeMaxDynamicSharedMemorySize, DSM_BYTES);

    // weight quantization (deterministic)
    k_wpart<<<5 * 64, 256>>>(win, wf1, wf2, wz, wmk);
    k_wfinal<<<5, 64>>>();
    k_wquant<<<(WQ_TOTAL + 255) / 256, 256>>>(win, wf1, wf2, wz, wmk);

    // h = bitlinear(cat, W_in)
    k_aq_cat<<<T_TOK, 128>>>(x, y, sp);
    k_gemm<0><<<dim3(DIM / 128, T_TOK / 128), 256, DSM_BYTES>>>(OFF_WIN, 0, K_CAT, DIM, 0, out);

    // g = gelu(bitlinear(h, W_fc1))
    k_aq_v<DIM><<<T_TOK, 128>>>(0);
    k_gemm<1><<<dim3(HID / 128, T_TOK / 128), 256, DSM_BYTES>>>(OFF_WFC1, 1, DIM, HID, 1, out);

    // h += bitlinear(g, W_fc2)
    k_aq_v<HID><<<T_TOK, 128>>>(1);
    k_gemm<2><<<dim3(DIM / 128, T_TOK / 128), 256, DSM_BYTES>>>(OFF_WFC2, 2, HID, DIM, 0, out);

    // z = bitlinear(h, W_z) -> d_out[0 : T*512]
    k_aq_v<DIM><<<T_TOK, 128>>>(0);
    k_gemm<0><<<dim3(DIM / 128, T_TOK / 128), 256, DSM_BYTES>>>(OFF_WZ, 3, DIM, DIM, 2, out);

    // focus_mask -> d_out[T*512 : T*512 + T]
    k_mask<<<T_TOK / 8, 256>>>(out + (size_t)T_TOK * DIM);
}

// round 14
// speedup vs baseline: 1.2304x; 1.0032x over previous
#include <cuda_runtime.h>
#include <cuda_bf16.h>
#include <cstdint>
#include <cstddef>
#include <math.h>

// ---------------------------------------------------------------------------
// Problem constants
// ---------------------------------------------------------------------------
#define T_TOK   41472          // 512*81 tokens = 324*128
#define DIM     512
#define HID     2048
#define K_CAT   1536
#define EPSF    1e-5f

// weight segment element offsets inside g_wq
#define OFF_WIN   0            // W_in   [512 ,1536]
#define OFF_WFC1  786432       // W_fc1  [2048, 512]
#define OFF_WFC2  1835008      // W_fc2  [512 ,2048]
#define OFF_WZ    2883584      // W_z    [512 , 512]
#define OFF_WM    3145728      // W_mask [1   , 512]
#define WQ_TOTAL  3146240

// GEMM tiling: 128x128x64, 256 threads, 3 smem buffers, 2 CTAs/SM
#define LDS64       72                     // row stride (bf16): 144B, odd chunks -> conflict-free
#define TILE_ELEMS  (128 * LDS64)          // 9216 bf16 per tile
#define STAGE_ELEMS (2 * TILE_ELEMS)       // A + B
#define DSM_BYTES   (3 * STAGE_ELEMS * 2)  // 110592 bytes

// ---------------------------------------------------------------------------
// Scratch (device globals; allocation-free)
// ---------------------------------------------------------------------------
__device__ __align__(256) __nv_bfloat16 g_qact[(size_t)T_TOK * 2048]; // quantized acts (bf16-held ints)
__device__ __align__(256) float         g_h  [(size_t)T_TOK * DIM];   // h (residual-updated in place)
__device__ __align__(256) float         g_g  [(size_t)T_TOK * HID];   // gelu output
__device__ __align__(256) __nv_bfloat16 g_wq [WQ_TOTAL];              // ternary weights as bf16
__device__ __align__(256) float         g_ainv[T_TOK];                // per-token absmax/127
__device__ __align__(256) float         g_wmean[5];                   // clip(mean|w|,1e-5)
__device__ __align__(256) double        g_part[5 * 64];               // deterministic partials

// ---------------------------------------------------------------------------
// Small helpers
// ---------------------------------------------------------------------------
__device__ __forceinline__ uint32_t smem_u32(const void* p) {
    uint32_t a;
    asm("{ .reg .u64 t; cvta.to.shared.u64 t, %1; cvt.u32.u64 %0, t; }" : "=r"(a) : "l"(p));
    return a;
}
__device__ __forceinline__ void cp16(uint32_t s, const void* g) {
    asm volatile("cp.async.cg.shared.global [%0], [%1], 16;" :: "r"(s), "l"(g));
}
__device__ __forceinline__ void cp_commit() {
    asm volatile("cp.async.commit_group;" ::: "memory");
}
__device__ __forceinline__ void cp_wait1() {
    asm volatile("cp.async.wait_group 1;" ::: "memory");
}
__device__ __forceinline__ void cp_wait0() {
    asm volatile("cp.async.wait_group 0;" ::: "memory");
}
__device__ __forceinline__ void ldsm4(uint32_t* r, uint32_t a) {
    asm volatile("ldmatrix.sync.aligned.m8n8.x4.shared.b16 {%0,%1,%2,%3}, [%4];"
                 : "=r"(r[0]), "=r"(r[1]), "=r"(r[2]), "=r"(r[3]) : "r"(a));
}
__device__ __forceinline__ void mma16816(float* c, const uint32_t* a, uint32_t b0, uint32_t b1) {
    asm volatile("mma.sync.aligned.m16n8k16.row.col.f32.bf16.bf16.f32 "
                 "{%0,%1,%2,%3}, {%4,%5,%6,%7}, {%8,%9}, {%0,%1,%2,%3};"
                 : "+f"(c[0]), "+f"(c[1]), "+f"(c[2]), "+f"(c[3])
                 : "r"(a[0]), "r"(a[1]), "r"(a[2]), "r"(a[3]), "r"(b0), "r"(b1));
}
__device__ __forceinline__ float gelu_exact(float v) {
    return 0.5f * v * (1.0f + erff(v * 0.7071067811865476f));
}
__device__ __forceinline__ uint32_t bpack2(float a, float b) {
    __nv_bfloat162 h;
    h.x = __float2bfloat16(a);
    h.y = __float2bfloat16(b);
    return *(uint32_t*)&h;
}
__device__ __forceinline__ float qv(float v, float sc) {
    return fminf(fmaxf(rintf(v * sc), -128.0f), 127.0f);
}

// ---------------------------------------------------------------------------
// Weight stats: deterministic |w| mean per segment (double accumulation)
// ---------------------------------------------------------------------------
__constant__ int c_seglen[5] = {786432, 1048576, 1048576, 262144, 512};

__global__ void k_wpart(const float* w0, const float* w1, const float* w2,
                        const float* w3, const float* w4) {
    __shared__ double red[256];
    int seg = blockIdx.x >> 6, chunk = blockIdx.x & 63;
    const float* w = (seg == 0) ? w0 : (seg == 1) ? w1 : (seg == 2) ? w2 : (seg == 3) ? w3 : w4;
    int len = c_seglen[seg];
    int clen = (len + 63) >> 6;
    int beg = chunk * clen;
    int end = min(beg + clen, len);
    double s = 0.0;
    for (int i = beg + threadIdx.x; i < end; i += 256) s += (double)fabsf(w[i]);
    red[threadIdx.x] = s;
    __syncthreads();
    for (int st = 128; st; st >>= 1) {
        if (threadIdx.x < st) red[threadIdx.x] += red[threadIdx.x + st];
        __syncthreads();
    }
    if (threadIdx.x == 0) g_part[blockIdx.x] = red[0];
}

__global__ void k_wfinal() {
    __shared__ double red[64];
    int seg = blockIdx.x;
    red[threadIdx.x] = g_part[seg * 64 + threadIdx.x];
    __syncthreads();
    for (int st = 32; st; st >>= 1) {
        if (threadIdx.x < st) red[threadIdx.x] += red[threadIdx.x + st];
        __syncthreads();
    }
    if (threadIdx.x == 0)
        g_wmean[seg] = fmaxf((float)(red[0] / (double)c_seglen[seg]), EPSF);
}

__global__ void k_wquant(const float* w0, const float* w1, const float* w2,
                         const float* w3, const float* w4) {
    int i = blockIdx.x * 256 + threadIdx.x;
    if (i >= WQ_TOTAL) return;
    int seg, off;
    const float* w;
    if (i < OFF_WFC1)      { seg = 0; off = i;            w = w0; }
    else if (i < OFF_WFC2) { seg = 1; off = i - OFF_WFC1; w = w1; }
    else if (i < OFF_WZ)   { seg = 2; off = i - OFF_WFC2; w = w2; }
    else if (i < OFF_WM)   { seg = 3; off = i - OFF_WZ;   w = w3; }
    else                   { seg = 4; off = i - OFF_WM;   w = w4; }
    float sc = 1.0f / g_wmean[seg];
    float q = fminf(fmaxf(rintf(w[off] * sc), -1.0f), 1.0f);
    g_wq[i] = __float2bfloat16(q);
}

// ---------------------------------------------------------------------------
// Activation quantization: per-token absmax int8 values held in bf16 (exact).
// 128 threads/token, values kept in registers, float4 in / bf16x2-pair out.
// isrc: 0 -> g_h, 1 -> g_g
// ---------------------------------------------------------------------------
template <int K>
__global__ void __launch_bounds__(128) k_aq_v(int isrc) {
    constexpr int V = K / 512;  // float4 per thread
    __shared__ float sm[4];
    const float4* x4 = (const float4*)(((isrc == 0) ? g_h : g_g) + (size_t)blockIdx.x * K);
    float4 v[V];
    float m = 0.0f;
#pragma unroll
    for (int i = 0; i < V; i++) {
        v[i] = x4[threadIdx.x + i * 128];
        m = fmaxf(m, fmaxf(fmaxf(fabsf(v[i].x), fabsf(v[i].y)),
                           fmaxf(fabsf(v[i].z), fabsf(v[i].w))));
    }
#pragma unroll
    for (int st = 16; st; st >>= 1) m = fmaxf(m, __shfl_xor_sync(0xFFFFFFFFu, m, st));
    if ((threadIdx.x & 31) == 0) sm[threadIdx.x >> 5] = m;
    __syncthreads();
    float amax = fmaxf(fmaxf(fmaxf(sm[0], sm[1]), fmaxf(sm[2], sm[3])), EPSF);
    float sc = 127.0f / amax;
    uint2* q2 = (uint2*)(g_qact + (size_t)blockIdx.x * K);
#pragma unroll
    for (int i = 0; i < V; i++) {
        uint2 u;
        u.x = bpack2(qv(v[i].x, sc), qv(v[i].y, sc));
        u.y = bpack2(qv(v[i].z, sc), qv(v[i].w, sc));
        q2[threadIdx.x + i * 128] = u;
    }
    if (threadIdx.x == 0) g_ainv[blockIdx.x] = amax * (1.0f / 127.0f);
}

// Stage-4 variant: quantize h (K=512) AND compute the mask head in the same
// pass. The mask dot is an f32 sum of exact small ints (|q·w| <= 127, sum
// <= 2^16) -> order-independent-exact, bit-identical to the old k_mask.
__global__ void __launch_bounds__(128) k_aq_mask(float* __restrict__ outMask) {
    __shared__ float sm[4];
    __shared__ float sd[4];
    const float4* x4 = (const float4*)(g_h + (size_t)blockIdx.x * DIM);
    float4 v = x4[threadIdx.x];
    float m = fmaxf(fmaxf(fabsf(v.x), fabsf(v.y)), fmaxf(fabsf(v.z), fabsf(v.w)));
#pragma unroll
    for (int st = 16; st; st >>= 1) m = fmaxf(m, __shfl_xor_sync(0xFFFFFFFFu, m, st));
    if ((threadIdx.x & 31) == 0) sm[threadIdx.x >> 5] = m;
    __syncthreads();
    float amax = fmaxf(fmaxf(fmaxf(sm[0], sm[1]), fmaxf(sm[2], sm[3])), EPSF);
    float sc = 127.0f / amax;

    float q0 = qv(v.x, sc), q1 = qv(v.y, sc), q2v = qv(v.z, sc), q3 = qv(v.w, sc);

    uint2 u;
    u.x = bpack2(q0, q1);
    u.y = bpack2(q2v, q3);
    ((uint2*)(g_qact + (size_t)blockIdx.x * DIM))[threadIdx.x] = u;

    // mask dot: thread t covers cols 4t..4t+3
    const __nv_bfloat162* wm2 = (const __nv_bfloat162*)(g_wq + OFF_WM);
    __nv_bfloat162 w01 = wm2[threadIdx.x * 2];
    __nv_bfloat162 w23 = wm2[threadIdx.x * 2 + 1];
    float d = q0 * __bfloat162float(w01.x) + q1 * __bfloat162float(w01.y)
            + q2v * __bfloat162float(w23.x) + q3 * __bfloat162float(w23.y);
#pragma unroll
    for (int st = 16; st; st >>= 1) d += __shfl_xor_sync(0xFFFFFFFFu, d, st);
    if ((threadIdx.x & 31) == 0) sd[threadIdx.x >> 5] = d;
    __syncthreads();
    if (threadIdx.x == 0) {
        float s = (sd[0] + sd[1]) + (sd[2] + sd[3]);
        float z = s * (amax * (1.0f / 127.0f)) * g_wmean[4];
        g_ainv[blockIdx.x] = amax * (1.0f / 127.0f);
        outMask[blockIdx.x] = 1.0f / (1.0f + expf(-z));
    }
}

// cat([x,y,s], -1) variant, K = 1536
__global__ void __launch_bounds__(128) k_aq_cat(const float* __restrict__ x,
                                                const float* __restrict__ y,
                                                const float* __restrict__ s) {
    __shared__ float sm[4];
    size_t row = blockIdx.x;
    float4 vx = ((const float4*)(x + row * DIM))[threadIdx.x];
    float4 vy = ((const float4*)(y + row * DIM))[threadIdx.x];
    float4 vs = ((const float4*)(s + row * DIM))[threadIdx.x];
    float m = fmaxf(fmaxf(fabsf(vx.x), fabsf(vx.y)), fmaxf(fabsf(vx.z), fabsf(vx.w)));
    m = fmaxf(m, fmaxf(fmaxf(fabsf(vy.x), fabsf(vy.y)), fmaxf(fabsf(vy.z), fabsf(vy.w))));
    m = fmaxf(m, fmaxf(fmaxf(fabsf(vs.x), fabsf(vs.y)), fmaxf(fabsf(vs.z), fabsf(vs.w))));
#pragma unroll
    for (int st = 16; st; st >>= 1) m = fmaxf(m, __shfl_xor_sync(0xFFFFFFFFu, m, st));
    if ((threadIdx.x & 31) == 0) sm[threadIdx.x >> 5] = m;
    __syncthreads();
    float amax = fmaxf(fmaxf(fmaxf(sm[0], sm[1]), fmaxf(sm[2], sm[3])), EPSF);
    float sc = 127.0f / amax;
    uint2* q2 = (uint2*)(g_qact + row * K_CAT);
    uint2 u;
    u.x = bpack2(qv(vx.x, sc), qv(vx.y, sc)); u.y = bpack2(qv(vx.z, sc), qv(vx.w, sc));
    q2[threadIdx.x] = u;
    u.x = bpack2(qv(vy.x, sc), qv(vy.y, sc)); u.y = bpack2(qv(vy.z, sc), qv(vy.w, sc));
    q2[threadIdx.x + 128] = u;
    u.x = bpack2(qv(vs.x, sc), qv(vs.y, sc)); u.y = bpack2(qv(vs.z, sc), qv(vs.w, sc));
    q2[threadIdx.x + 256] = u;
    if (threadIdx.x == 0) g_ainv[row] = amax * (1.0f / 127.0f);
}

// ---------------------------------------------------------------------------
// GEMM: C[m,n] = epi( (sum_k Aq[m,k] * Wq[n,k]) * ainv[m] * wmean[widx] )
// Block 128x128, BK=64, 256 threads, 3-buffer depth-2 cp.async pipeline with
// interleaved quarter-fills and register double-buffered LDSM fragments.
// EPI: 0 = store, 1 = gelu+store, 2 = residual add
// csel: 0 -> g_h, 1 -> g_g, 2 -> Cext (d_out)
// ---------------------------------------------------------------------------
template <int EPI>
__global__ void __launch_bounds__(256, 2) k_gemm(int woff, int widx, int K, int N,
                                                 int csel, float* Cext) {
    extern __shared__ __align__(16) __nv_bfloat16 dsm[];

    const __nv_bfloat16* __restrict__ A = g_qact;
    const __nv_bfloat16* __restrict__ W = g_wq + woff;
    float* __restrict__ C = (csel == 0) ? g_h : (csel == 1) ? g_g : Cext;

    const int tid  = threadIdx.x;
    const int lane = tid & 31;
    const int wrp  = tid >> 5;
    const int wm   = wrp & 3;           // 4 warp rows  (32 rows each)
    const int wn   = wrp >> 2;          // 2 warp cols  (64 cols each)
    const int m0   = blockIdx.y * 128;
    const int n0   = blockIdx.x * 128;

    float acc[2][8][4];
#pragma unroll
    for (int a = 0; a < 2; a++)
#pragma unroll
        for (int b = 0; b < 8; b++)
#pragma unroll
            for (int c = 0; c < 4; c++) acc[a][b][c] = 0.0f;

    uint32_t aOff[2], bOff[4];
#pragma unroll
    for (int mf = 0; mf < 2; mf++)
        aOff[mf] = (uint32_t)((wm * 32 + mf * 16 + (lane & 15)) * LDS64 + (lane >> 4) * 8);
#pragma unroll
    for (int nf2 = 0; nf2 < 4; nf2++)
        bOff[nf2] = (uint32_t)((wn * 64 + nf2 * 16 + (lane >> 4) * 8 + (lane & 7)) * LDS64
                               + ((lane >> 3) & 1) * 8);

    const int nk = K >> 6;   // BK = 64

    auto load_stage = [&](int ks, int buf) {
        const int k0 = ks << 6;
        __nv_bfloat16* sA = dsm + buf * STAGE_ELEMS;
        __nv_bfloat16* sB = sA + TILE_ELEMS;
#pragma unroll
        for (int i = 0; i < 4; i++) {
            int c   = tid + i * 256;
            int row = c >> 3;
            int ch  = c & 7;
            cp16(smem_u32(sA + row * LDS64 + ch * 8),
                 A + (size_t)(m0 + row) * K + k0 + ch * 8);
        }
#pragma unroll
        for (int i = 0; i < 4; i++) {
            int c   = tid + i * 256;
            int row = c >> 3;
            int ch  = c & 7;
            cp16(smem_u32(sB + row * LDS64 + ch * 8),
                 W + (size_t)(n0 + row) * K + k0 + ch * 8);
        }
        cp_commit();
    };

    auto quarter_fill = [&](int ks, int buf, int q) {
        const int k0 = ks << 6;
        __nv_bfloat16* sA = dsm + buf * STAGE_ELEMS;
        __nv_bfloat16* sB = sA + TILE_ELEMS;
        int c   = tid + q * 256;
        int row = c >> 3;
        int ch  = c & 7;
        cp16(smem_u32(sA + row * LDS64 + ch * 8),
             A + (size_t)(m0 + row) * K + k0 + ch * 8);
        cp16(smem_u32(sB + row * LDS64 + ch * 8),
             W + (size_t)(n0 + row) * K + k0 + ch * 8);
    };

    load_stage(0, 0);
    load_stage(1, 1);

    int buf = 0;
    for (int ks = 0; ks < nk; ks++) {
        if (ks + 1 < nk) cp_wait1(); else cp_wait0();
        __syncthreads();
        const bool pf = (ks + 2 < nk);
        int nb = buf + 2; if (nb >= 3) nb -= 3;

        const uint32_t baseA = smem_u32(dsm + buf * STAGE_ELEMS);
        const uint32_t baseB = baseA + TILE_ELEMS * 2u;

        uint32_t afr[2][2][4];   // [kst parity][mf][reg]
        uint32_t bfr[2][4];      // [nf2 parity][reg]

        ldsm4(afr[0][0], baseA + (aOff[0] + 0) * 2u);
        ldsm4(afr[0][1], baseA + (aOff[1] + 0) * 2u);
        ldsm4(bfr[0],    baseB + (bOff[0] + 0) * 2u);

#pragma unroll
        for (int kst = 0; kst < 4; kst++) {
            const int cur = kst & 1;
            const uint32_t kb = (uint32_t)(kst * 16);
            if (pf) quarter_fill(ks + 2, nb, kst);
            if (kst < 3) {
                ldsm4(afr[cur ^ 1][0], baseA + (aOff[0] + kb + 16) * 2u);
                ldsm4(afr[cur ^ 1][1], baseA + (aOff[1] + kb + 16) * 2u);
            }
#pragma unroll
            for (int nf2 = 0; nf2 < 4; nf2++) {
                const int bb = nf2 & 1;
                if (nf2 < 3) {
                    ldsm4(bfr[bb ^ 1], baseB + (bOff[nf2 + 1] + kb) * 2u);
                } else if (kst < 3) {
                    ldsm4(bfr[bb ^ 1], baseB + (bOff[0] + kb + 16) * 2u);
                }
#pragma unroll
                for (int mf = 0; mf < 2; mf++) {
                    mma16816(acc[mf][nf2 * 2 + 0], afr[cur][mf], bfr[bb][0], bfr[bb][1]);
                    mma16816(acc[mf][nf2 * 2 + 1], afr[cur][mf], bfr[bb][2], bfr[bb][3]);
                }
            }
        }
        if (pf) cp_commit();
        if (++buf == 3) buf = 0;
    }

    // ---------------- epilogue ----------------
    const float ws  = g_wmean[widx];
    const int   tm  = lane >> 2;
    const int   tn2 = (lane & 3) * 2;
#pragma unroll
    for (int mf = 0; mf < 2; mf++) {
        const int r0 = m0 + wm * 32 + mf * 16 + tm;
        const int r1 = r0 + 8;
        const float s0 = g_ainv[r0] * ws;
        const float s1 = g_ainv[r1] * ws;
#pragma unroll
        for (int nf = 0; nf < 8; nf++) {
            const int c0 = n0 + wn * 64 + nf * 8 + tn2;
            const size_t i0 = (size_t)r0 * N + c0;
            const size_t i1 = (size_t)r1 * N + c0;
            float v00 = acc[mf][nf][0] * s0, v01 = acc[mf][nf][1] * s0;
            float v10 = acc[mf][nf][2] * s1, v11 = acc[mf][nf][3] * s1;
            if (EPI == 0) {
                C[i0] = v00; C[i0 + 1] = v01; C[i1] = v10; C[i1 + 1] = v11;
            } else if (EPI == 1) {
                C[i0] = gelu_exact(v00); C[i0 + 1] = gelu_exact(v01);
                C[i1] = gelu_exact(v10); C[i1 + 1] = gelu_exact(v11);
            } else {
                C[i0] += v00; C[i0 + 1] += v01; C[i1] += v10; C[i1 + 1] += v11;
            }
        }
    }
}

// ---------------------------------------------------------------------------
// Launch
// ---------------------------------------------------------------------------
extern "C" void kernel_launch(void* const* d_in, const int* in_sizes, int n_in,
                              void* d_out, int out_size) {
    const float* x   = (const float*)d_in[0];
    const float* y   = (const float*)d_in[1];
    const float* sp  = (const float*)d_in[2];
    const float* win = (const float*)d_in[3];
    const float* wf1 = (const float*)d_in[4];
    const float* wf2 = (const float*)d_in[5];
    const float* wz  = (const float*)d_in[6];
    const float* wmk = (const float*)d_in[7];
    float* out = (float*)d_out;

    cudaFuncSetAttribute(k_gemm<0>, cudaFuncAttributeMaxDynamicSharedMemorySize, DSM_BYTES);
    cudaFuncSetAttribute(k_gemm<1>, cudaFuncAttributeMaxDynamicSharedMemorySize, DSM_BYTES);
    cudaFuncSetAttribute(k_gemm<2>, cudaFuncAttributeMaxDynamicSharedMemorySize, DSM_BYTES);

    // weight quantization (deterministic)
    k_wpart<<<5 * 64, 256>>>(win, wf1, wf2, wz, wmk);
    k_wfinal<<<5, 64>>>();
    k_wquant<<<(WQ_TOTAL + 255) / 256, 256>>>(win, wf1, wf2, wz, wmk);

    // h = bitlinear(cat, W_in)
    k_aq_cat<<<T_TOK, 128>>>(x, y, sp);
    k_gemm<0><<<dim3(DIM / 128, T_TOK / 128), 256, DSM_BYTES>>>(OFF_WIN, 0, K_CAT, DIM, 0, out);

    // g = gelu(bitlinear(h, W_fc1))
    k_aq_v<DIM><<<T_TOK, 128>>>(0);
    k_gemm<1><<<dim3(HID / 128, T_TOK / 128), 256, DSM_BYTES>>>(OFF_WFC1, 1, DIM, HID, 1, out);

    // h += bitlinear(g, W_fc2)
    k_aq_v<HID><<<T_TOK, 128>>>(1);
    k_gemm<2><<<dim3(DIM / 128, T_TOK / 128), 256, DSM_BYTES>>>(OFF_WFC2, 2, HID, DIM, 0, out);

    // quantize h + fused mask head -> d_out[T*512 : T*512 + T]
    k_aq_mask<<<T_TOK, 128>>>(out + (size_t)T_TOK * DIM);

    // z = bitlinear(h, W_z) -> d_out[0 : T*512]
    k_gemm<0><<<dim3(DIM / 128, T_TOK / 128), 256, DSM_BYTES>>>(OFF_WZ, 3, DIM, DIM, 2, out);
}